// round 15
// baseline (speedup 1.0000x reference)
#include <cuda_runtime.h>
#include <cuda_bf16.h>
#include <cuda_fp16.h>
#include <math.h>
#include <stdint.h>

#define Bz  4
#define Tt  2048
#define STt 2048
#define Cc  1024
#define Hh  16
#define Dd  64
#define MROWS (Bz * STt)   // 8192
#define GK 1024

// ---------------- scratch (static device arrays) ---------------------------
__device__ __nv_bfloat16 g_xh[(size_t)MROWS * Cc];
__device__ __nv_bfloat16 g_xl[(size_t)MROWS * Cc];
__device__ __nv_bfloat16 g_sxh[(size_t)MROWS * Cc];
__device__ __nv_bfloat16 g_sxl[(size_t)MROWS * Cc];
__device__ __nv_bfloat16 g_qh[(size_t)MROWS * Cc], g_ql[(size_t)MROWS * Cc];
__device__ __nv_bfloat16 g_kh[(size_t)MROWS * Cc], g_kl[(size_t)MROWS * Cc];
__device__ __nv_bfloat16 g_wqh[(size_t)Cc * Cc], g_wql[(size_t)Cc * Cc];
__device__ __nv_bfloat16 g_wkh[(size_t)Cc * Cc], g_wkl[(size_t)Cc * Cc];
// fp16 path
__device__ __half g_xh16[(size_t)MROWS * Cc], g_xl16[(size_t)MROWS * Cc];
__device__ __half g_y16[(size_t)MROWS * Cc];
__device__ __half g_v16[(size_t)MROWS * Cc];
__device__ __half g_wv16[(size_t)Cc * Cc], g_wc16[(size_t)Cc * Cc];

// ---------------- helpers ---------------------------------------------------
__device__ __forceinline__ uint32_t smem_u32(const void* p) {
    uint32_t a;
    asm("{ .reg .u64 t; cvta.to.shared.u64 t, %1; cvt.u32.u64 %0, t; }"
        : "=r"(a) : "l"(p));
    return a;
}
__device__ __forceinline__ void ldsm_x4(uint32_t* r, uint32_t addr) {
    asm volatile("ldmatrix.sync.aligned.m8n8.x4.shared.b16 {%0,%1,%2,%3}, [%4];"
                 : "=r"(r[0]), "=r"(r[1]), "=r"(r[2]), "=r"(r[3]) : "r"(addr));
}
__device__ __forceinline__ void ldsm_x4_t(uint32_t* r, uint32_t addr) {
    asm volatile("ldmatrix.sync.aligned.m8n8.x4.trans.shared.b16 {%0,%1,%2,%3}, [%4];"
                 : "=r"(r[0]), "=r"(r[1]), "=r"(r[2]), "=r"(r[3]) : "r"(addr));
}
__device__ __forceinline__ void mma16816(float* d, const uint32_t* a, const uint32_t* b) {
    asm volatile("mma.sync.aligned.m16n8k16.row.col.f32.bf16.bf16.f32 "
                 "{%0,%1,%2,%3}, {%4,%5,%6,%7}, {%8,%9}, {%0,%1,%2,%3};"
                 : "+f"(d[0]), "+f"(d[1]), "+f"(d[2]), "+f"(d[3])
                 : "r"(a[0]), "r"(a[1]), "r"(a[2]), "r"(a[3]), "r"(b[0]), "r"(b[1]));
}
__device__ __forceinline__ void mma16816h(float* d, const uint32_t* a, const uint32_t* b) {
    asm volatile("mma.sync.aligned.m16n8k16.row.col.f32.f16.f16.f32 "
                 "{%0,%1,%2,%3}, {%4,%5,%6,%7}, {%8,%9}, {%0,%1,%2,%3};"
                 : "+f"(d[0]), "+f"(d[1]), "+f"(d[2]), "+f"(d[3])
                 : "r"(a[0]), "r"(a[1]), "r"(a[2]), "r"(a[3]), "r"(b[0]), "r"(b[1]));
}
__device__ __forceinline__ uint32_t h2_bits(__half2 h) {
    union { __half2 h; uint32_t u; } cv; cv.h = h; return cv.u;
}

// ---------------------------------------------------------------------------
// One prep kernel. Modes: 0 bf16 hi/lo split, 2 fp16 round,
// 3 fused x: bf16 hi/lo + fp16 hi/lo from one read.
// ---------------------------------------------------------------------------
struct PJob { const float* s; void* h; void* l; void* h2; void* l2; int start; int n4; int mode; };
struct PJobs { PJob j[6]; };

__global__ void prep_all(PJobs J)
{
    int i = blockIdx.x * blockDim.x + threadIdx.x;
    #pragma unroll
    for (int w = 0; w < 6; w++) {
        const PJob jb = J.j[w];
        if (i >= jb.start && i < jb.start + jb.n4) {
            int k = i - jb.start;
            float4 v = ((const float4*)jb.s)[k];
            if (jb.mode == 0 || jb.mode == 3) {
                __nv_bfloat162* hp = (__nv_bfloat162*)jb.h;
                __nv_bfloat162* lp = (__nv_bfloat162*)jb.l;
                __nv_bfloat16 h0 = __float2bfloat16(v.x), h1 = __float2bfloat16(v.y);
                __nv_bfloat16 h2 = __float2bfloat16(v.z), h3 = __float2bfloat16(v.w);
                hp[2*k]   = __nv_bfloat162(h0, h1);
                hp[2*k+1] = __nv_bfloat162(h2, h3);
                lp[2*k]   = __nv_bfloat162(__float2bfloat16(v.x - __bfloat162float(h0)),
                                           __float2bfloat16(v.y - __bfloat162float(h1)));
                lp[2*k+1] = __nv_bfloat162(__float2bfloat16(v.z - __bfloat162float(h2)),
                                           __float2bfloat16(v.w - __bfloat162float(h3)));
            }
            if (jb.mode == 3) {
                __half2* hp = (__half2*)jb.h2;
                __half2* lp = (__half2*)jb.l2;
                __half2 H0 = __floats2half2_rn(v.x, v.y);
                __half2 H1 = __floats2half2_rn(v.z, v.w);
                hp[2*k] = H0; hp[2*k+1] = H1;
                lp[2*k] = __floats2half2_rn(v.x - __half2float(__low2half(H0)),
                                            v.y - __half2float(__high2half(H0)));
                lp[2*k+1] = __floats2half2_rn(v.z - __half2float(__low2half(H1)),
                                              v.w - __half2float(__high2half(H1)));
            }
            if (jb.mode == 2) {
                __half2* hp = (__half2*)jb.h;
                hp[2*k]   = __floats2half2_rn(v.x, v.y);
                hp[2*k+1] = __floats2half2_rn(v.z, v.w);
            }
            return;
        }
    }
}

// ---------------------------------------------------------------------------
// Tiling constants (R12 layout: BK=32, 80B rows)
// ---------------------------------------------------------------------------
#define BM 128
#define BN 128
#define BK 32
#define NST (GK / BK)                // 32
#define PADE 40
#define ROWB (PADE * 2)              // 80 B/row
#define MAT_BYTES (128 * ROWB)       // 10240
#define STAGE_BYTES (4 * MAT_BYTES)  // 40960 (bf16x3)
#define STAGE3_BYTES (3 * MAT_BYTES) // 30720 (fp16x2)
#define STAGE1_BYTES (2 * MAT_BYTES) // 20480 (fp16x1)
#define PROJ_SMEM (2 * STAGE_BYTES)  // 81920 (ring-2; v path uses 61440 of it)
#define GEMM1_SMEM (2 * STAGE1_BYTES) // 40960 (ring-2)

// ---------------------------------------------------------------------------
// Merged q/k/v projections, 1D interleaved grid: z = bid%3 mixes heavy (q,k)
// and light (v) CTAs in every wave -> single partial tail instead of three.
// ---------------------------------------------------------------------------
__global__ __launch_bounds__(256, 2)
void proj_qkv(const __nv_bfloat16* __restrict__ sxh, const __nv_bfloat16* __restrict__ sxl,
              const __nv_bfloat16* __restrict__ xh,  const __nv_bfloat16* __restrict__ xl,
              const __nv_bfloat16* __restrict__ wqh, const __nv_bfloat16* __restrict__ wql,
              const __nv_bfloat16* __restrict__ wkh, const __nv_bfloat16* __restrict__ wkl,
              const __half* __restrict__ xh16, const __half* __restrict__ xl16,
              const __half* __restrict__ wv16,
              __nv_bfloat16* __restrict__ qhO, __nv_bfloat16* __restrict__ qlO,
              __nv_bfloat16* __restrict__ khO, __nv_bfloat16* __restrict__ klO,
              __half* __restrict__ v16O)
{
    extern __shared__ char dsm[];
    const uint32_t sb = smem_u32(dsm);

    const int tid = threadIdx.x;
    const int wid = tid >> 5, lid = tid & 31;
    const int wm = wid & 3, wn = wid >> 2;

    // interleaved mapping: z fastest, then n, then m
    const int bid = blockIdx.x;
    const int z   = bid % 3;
    const int rem = bid / 3;
    const int n0  = (rem & 7) * BN;    // Cc/BN = 8
    const int m0  = (rem >> 3) * BM;

    const uint32_t aOff = (uint32_t)(wm * 32 + (lid & 15)) * ROWB + ((lid >> 4) * 8) * 2;
    const uint32_t bOff = 2u * MAT_BYTES
        + (uint32_t)(wn * 64 + ((lid >> 4) & 1) * 8 + (lid & 7)) * ROWB
        + (((lid >> 3) & 1) * 8) * 2;
    const int erow = m0 + wm * 32 + (lid >> 2);
    const int ecol = n0 + wn * 64 + (lid & 3) * 2;

    float acc[2][8][4];
    #pragma unroll
    for (int a = 0; a < 2; a++)
        #pragma unroll
        for (int b = 0; b < 8; b++)
            #pragma unroll
            for (int c = 0; c < 4; c++) acc[a][b][c] = 0.f;

    if (z < 2) {
        // ================= bf16x3 path (q or k), ring-2 =================
        const __nv_bfloat16* Ah = (z == 0) ? sxh : xh;
        const __nv_bfloat16* Al = (z == 0) ? sxl : xl;
        const __nv_bfloat16* Wh = (z == 0) ? wqh : wkh;
        const __nv_bfloat16* Wl = (z == 0) ? wql : wkl;
        __nv_bfloat16* OutH = (z == 0) ? qhO : khO;
        __nv_bfloat16* OutL = (z == 0) ? qlO : klO;

        const int lmm = tid >> 6;
        const int l64 = tid & 63;
        const __nv_bfloat16* lg = (lmm == 0) ? Ah : (lmm == 1) ? Al : (lmm == 2) ? Wh : Wl;
        const int lr0 = (lmm < 2) ? m0 : n0;
        const uint32_t lsm = (uint32_t)lmm * MAT_BYTES;

        #define ISSUE_STAGE(t, buf) do {                                              \
            uint32_t base_ = sb + (uint32_t)(buf) * STAGE_BYTES + lsm;                 \
            const __nv_bfloat16* gp0_ = lg + (size_t)lr0 * GK + (t) * BK;              \
            _Pragma("unroll")                                                          \
            for (int p_ = 0; p_ < 8; p_++) {                                           \
                int i_ = p_ * 64 + l64;                                                \
                int row_ = i_ >> 2, vec_ = i_ & 3;                                     \
                const void* gp_ = gp0_ + (size_t)row_ * GK + vec_ * 8;                 \
                uint32_t sp_ = base_ + (uint32_t)(row_ * ROWB + vec_ * 16);            \
                asm volatile("cp.async.cg.shared.global [%0], [%1], 16;"               \
                             :: "r"(sp_), "l"(gp_));                                   \
            }                                                                          \
            asm volatile("cp.async.commit_group;" ::: "memory");                       \
        } while (0)

        ISSUE_STAGE(0, 0);

        for (int t = 0; t < NST; t++) {
            asm volatile("cp.async.wait_group 0;" ::: "memory");
            __syncthreads();
            if (t + 1 < NST) ISSUE_STAGE(t + 1, (t + 1) & 1);

            const uint32_t st = sb + (uint32_t)(t & 1) * STAGE_BYTES;
            #pragma unroll
            for (int kk = 0; kk < 2; kk++) {
                const uint32_t ab = st + aOff + kk * 32;
                uint32_t ah0[4], ah1[4], al0[4], al1[4];
                ldsm_x4(ah0, ab);
                ldsm_x4(ah1, ab + 16 * ROWB);
                ldsm_x4(al0, ab + MAT_BYTES);
                ldsm_x4(al1, ab + MAT_BYTES + 16 * ROWB);

                const uint32_t bb = st + bOff + kk * 32;
                #pragma unroll
                for (int pp = 0; pp < 2; pp++) {
                    uint32_t bh[2][4], bl[2][4];
                    const uint32_t b0 = bb + (uint32_t)(pp * 2) * 16 * ROWB;
                    ldsm_x4(bh[0], b0);
                    ldsm_x4(bh[1], b0 + 16 * ROWB);
                    ldsm_x4(bl[0], b0 + MAT_BYTES);
                    ldsm_x4(bl[1], b0 + MAT_BYTES + 16 * ROWB);
                    #pragma unroll
                    for (int j = 0; j < 2; j++)
                        #pragma unroll
                        for (int q = 0; q < 2; q++) {
                            mma16816(acc[0][(pp * 2 + j) * 2 + q], ah0, bh[j] + q * 2);
                            mma16816(acc[1][(pp * 2 + j) * 2 + q], ah1, bh[j] + q * 2);
                            mma16816(acc[0][(pp * 2 + j) * 2 + q], ah0, bl[j] + q * 2);
                            mma16816(acc[1][(pp * 2 + j) * 2 + q], ah1, bl[j] + q * 2);
                            mma16816(acc[0][(pp * 2 + j) * 2 + q], al0, bh[j] + q * 2);
                            mma16816(acc[1][(pp * 2 + j) * 2 + q], al1, bh[j] + q * 2);
                        }
                }
            }
        }
        #undef ISSUE_STAGE

        #pragma unroll
        for (int mt = 0; mt < 2; mt++)
            #pragma unroll
            for (int nt = 0; nt < 8; nt++)
                #pragma unroll
                for (int rr = 0; rr < 2; rr++) {
                    float f0 = acc[mt][nt][rr * 2], f1 = acc[mt][nt][rr * 2 + 1];
                    __nv_bfloat16 h0 = __float2bfloat16(f0);
                    __nv_bfloat16 h1 = __float2bfloat16(f1);
                    size_t idx = (size_t)(erow + mt * 16 + rr * 8) * Cc + ecol + nt * 8;
                    *(__nv_bfloat162*)(OutH + idx) = __nv_bfloat162(h0, h1);
                    *(__nv_bfloat162*)(OutL + idx) =
                        __nv_bfloat162(__float2bfloat16(f0 - __bfloat162float(h0)),
                                       __float2bfloat16(f1 - __bfloat162float(h1)));
                }
    } else {
        // ================= fp16x2 path (v), ring-2 =================
        const int lmm = tid >> 6;
        const int l64 = tid & 63;
        const __half* lg = (lmm == 0) ? xh16 : (lmm == 1) ? xl16 : wv16;
        const int lr0 = (lmm < 2) ? m0 : (lmm == 2 ? n0 : n0 + 64);
        const uint32_t lsm = (lmm < 2) ? (uint32_t)lmm * MAT_BYTES
                                       : 2u * MAT_BYTES + (lmm == 3 ? 64u * ROWB : 0u);
        const int lit = (lmm < 2) ? 8 : 4;

        #define ISSUE_ST16(t, buf) do {                                               \
            uint32_t base_ = sb + (uint32_t)(buf) * STAGE3_BYTES + lsm;                \
            const __half* gp0_ = lg + (size_t)lr0 * GK + (t) * BK;                     \
            _Pragma("unroll")                                                          \
            for (int p_ = 0; p_ < 8; p_++) {                                           \
                if (p_ < lit) {                                                        \
                    int i_ = p_ * 64 + l64;                                            \
                    int row_ = i_ >> 2, vec_ = i_ & 3;                                 \
                    const void* gp_ = gp0_ + (size_t)row_ * GK + vec_ * 8;             \
                    uint32_t sp_ = base_ + (uint32_t)(row_ * ROWB + vec_ * 16);        \
                    asm volatile("cp.async.cg.shared.global [%0], [%1], 16;"           \
                                 :: "r"(sp_), "l"(gp_));                               \
                }                                                                      \
            }                                                                          \
            asm volatile("cp.async.commit_group;" ::: "memory");                       \
        } while (0)

        ISSUE_ST16(0, 0);

        for (int t = 0; t < NST; t++) {
            asm volatile("cp.async.wait_group 0;" ::: "memory");
            __syncthreads();
            if (t + 1 < NST) ISSUE_ST16(t + 1, (t + 1) & 1);

            const uint32_t st = sb + (uint32_t)(t & 1) * STAGE3_BYTES;
            #pragma unroll
            for (int kk = 0; kk < 2; kk++) {
                const uint32_t ab = st + aOff + kk * 32;
                uint32_t ah0[4], ah1[4], al0[4], al1[4];
                ldsm_x4(ah0, ab);
                ldsm_x4(ah1, ab + 16 * ROWB);
                ldsm_x4(al0, ab + MAT_BYTES);
                ldsm_x4(al1, ab + MAT_BYTES + 16 * ROWB);

                const uint32_t bb = st + bOff + kk * 32;
                #pragma unroll
                for (int pp = 0; pp < 2; pp++) {
                    uint32_t w[2][4];
                    const uint32_t b0 = bb + (uint32_t)(pp * 2) * 16 * ROWB;
                    ldsm_x4(w[0], b0);
                    ldsm_x4(w[1], b0 + 16 * ROWB);
                    #pragma unroll
                    for (int j = 0; j < 2; j++)
                        #pragma unroll
                        for (int q = 0; q < 2; q++) {
                            mma16816h(acc[0][(pp * 2 + j) * 2 + q], ah0, w[j] + q * 2);
                            mma16816h(acc[1][(pp * 2 + j) * 2 + q], ah1, w[j] + q * 2);
                            mma16816h(acc[0][(pp * 2 + j) * 2 + q], al0, w[j] + q * 2);
                            mma16816h(acc[1][(pp * 2 + j) * 2 + q], al1, w[j] + q * 2);
                        }
                }
            }
        }
        #undef ISSUE_ST16

        #pragma unroll
        for (int mt = 0; mt < 2; mt++)
            #pragma unroll
            for (int nt = 0; nt < 8; nt++) {
                *(__half2*)(v16O + (size_t)(erow + mt * 16) * Cc + ecol + nt * 8) =
                    __floats2half2_rn(acc[mt][nt][0], acc[mt][nt][1]);
                *(__half2*)(v16O + (size_t)(erow + mt * 16 + 8) * Cc + ecol + nt * 8) =
                    __floats2half2_rn(acc[mt][nt][2], acc[mt][nt][3]);
            }
    }
}

// ---------------------------------------------------------------------------
// fp16 1-term GEMM (out projection), BK=32, ring-2 (R12): Out = y16 @ Wc16^T.
// ---------------------------------------------------------------------------
__global__ __launch_bounds__(256, 2)
void gemm_mma_fp16x1(const __half* __restrict__ A,
                     const __half* __restrict__ W,
                     float* __restrict__ OutF)
{
    extern __shared__ char dsm[];
    const uint32_t sb = smem_u32(dsm);

    const int tid = threadIdx.x;
    const int wid = tid >> 5, lid = tid & 31;
    const int wm = wid & 3, wn = wid >> 2;
    const int m0 = blockIdx.y * BM, n0 = blockIdx.x * BN;

    const int lmm = tid >> 6;
    const int l64 = tid & 63;
    const __half* lg = (lmm < 2) ? A : W;
    const int lr0 = ((lmm == 0) ? m0 : (lmm == 1) ? m0 + 64 : (lmm == 2) ? n0 : n0 + 64);
    const uint32_t lsm = ((lmm & 1) ? 64u * ROWB : 0u) + ((lmm >= 2) ? (uint32_t)MAT_BYTES : 0u);

    float acc[2][8][4];
    #pragma unroll
    for (int a = 0; a < 2; a++)
        #pragma unroll
        for (int b = 0; b < 8; b++)
            #pragma unroll
            for (int c = 0; c < 4; c++) acc[a][b][c] = 0.f;

    const uint32_t aOff = (uint32_t)(wm * 32 + (lid & 15)) * ROWB + ((lid >> 4) * 8) * 2;
    const uint32_t bOff = 1u * MAT_BYTES
        + (uint32_t)(wn * 64 + ((lid >> 4) & 1) * 8 + (lid & 7)) * ROWB
        + (((lid >> 3) & 1) * 8) * 2;

    #define ISSUE_ST1(t, buf) do {                                                \
        uint32_t base_ = sb + (uint32_t)(buf) * STAGE1_BYTES + lsm;                \
        const __half* gp0_ = lg + (size_t)lr0 * GK + (t) * BK;                     \
        _Pragma("unroll")                                                          \
        for (int p_ = 0; p_ < 4; p_++) {                                           \
            int i_ = p_ * 64 + l64;                                                \
            int row_ = i_ >> 2, vec_ = i_ & 3;                                     \
            const void* gp_ = gp0_ + (size_t)row_ * GK + vec_ * 8;                 \
            uint32_t sp_ = base_ + (uint32_t)(row_ * ROWB + vec_ * 16);            \
            asm volatile("cp.async.cg.shared.global [%0], [%1], 16;"               \
                         :: "r"(sp_), "l"(gp_));                                   \
        }                                                                          \
        asm volatile("cp.async.commit_group;" ::: "memory");                       \
    } while (0)

    ISSUE_ST1(0, 0);

    for (int t = 0; t < NST; t++) {
        asm volatile("cp.async.wait_group 0;" ::: "memory");
        __syncthreads();
        if (t + 1 < NST) ISSUE_ST1(t + 1, (t + 1) & 1);

        const uint32_t st = sb + (uint32_t)(t & 1) * STAGE1_BYTES;
        #pragma unroll
        for (int kk = 0; kk < 2; kk++) {
            const uint32_t ab = st + aOff + kk * 32;
            uint32_t ah0[4], ah1[4];
            ldsm_x4(ah0, ab);
            ldsm_x4(ah1, ab + 16 * ROWB);

            const uint32_t bb = st + bOff + kk * 32;
            #pragma unroll
            for (int pp = 0; pp < 2; pp++) {
                uint32_t w[2][4];
                const uint32_t b0 = bb + (uint32_t)(pp * 2) * 16 * ROWB;
                ldsm_x4(w[0], b0);
                ldsm_x4(w[1], b0 + 16 * ROWB);
                #pragma unroll
                for (int j = 0; j < 2; j++)
                    #pragma unroll
                    for (int q = 0; q < 2; q++) {
                        mma16816h(acc[0][(pp * 2 + j) * 2 + q], ah0, w[j] + q * 2);
                        mma16816h(acc[1][(pp * 2 + j) * 2 + q], ah1, w[j] + q * 2);
                    }
            }
        }
    }
    #undef ISSUE_ST1

    const int erow = m0 + wm * 32 + (lid >> 2);
    const int ecol = n0 + wn * 64 + (lid & 3) * 2;
    #pragma unroll
    for (int mt = 0; mt < 2; mt++)
        #pragma unroll
        for (int nt = 0; nt < 8; nt++) {
            *(float2*)(OutF + (size_t)(erow + mt * 16) * Cc + ecol + nt * 8) =
                make_float2(acc[mt][nt][0], acc[mt][nt][1]);
            *(float2*)(OutF + (size_t)(erow + mt * 16 + 8) * Cc + ecol + nt * 8) =
                make_float2(acc[mt][nt][2], acc[mt][nt][3]);
        }
}

// ---------------------------------------------------------------------------
// Flash attention (R12 version): QK^T bf16x3; PV single-fp16 P; fp16 y.
// Ring-3 KV; Q region reused as KV buffer 2; 2 CTAs/SM.
// ---------------------------------------------------------------------------
#define KROWB 144
#define KMAT  (64 * KROWB)            // 9216
#define KVSTAGE3 (3 * KMAT)           // 27648
#define QMAT  (128 * KROWB)           // 18432
#define QOFF  (2 * KVSTAGE3)          // 55296 == start of KV buffer 2
#define FLASH_SMEM (QOFF + 2 * QMAT)  // 92160
#define NKV (Tt / 64)

__global__ __launch_bounds__(256, 2)
void flash_mma(const __nv_bfloat16* __restrict__ qh, const __nv_bfloat16* __restrict__ ql,
               const __nv_bfloat16* __restrict__ kh, const __nv_bfloat16* __restrict__ kl,
               const __half* __restrict__ v16,
               __half* __restrict__ y16)
{
    extern __shared__ char dsm[];
    const uint32_t sb = smem_u32(dsm);

    const int tid = threadIdx.x;
    const int wid = tid >> 5, lid = tid & 31;
    const int i0 = blockIdx.x * 128;
    const int h  = blockIdx.y;
    const int b  = blockIdx.z;

    {
        const int qm = tid >> 7;
        const int l128 = tid & 127;
        const __nv_bfloat16* qg = (qm == 0) ? qh : ql;
        const uint32_t qsm = sb + QOFF + (uint32_t)qm * QMAT;
        #pragma unroll
        for (int it = 0; it < 8; it++) {
            int idx = it * 128 + l128;
            int row = idx >> 3, ch = idx & 7;
            const void* gp = qg + ((size_t)(b * STt + i0 + row)) * Cc + h * Dd + ch * 8;
            uint32_t sp = qsm + (uint32_t)(row * KROWB + ch * 16);
            asm volatile("cp.async.cg.shared.global [%0], [%1], 16;" :: "r"(sp), "l"(gp));
        }
        asm volatile("cp.async.commit_group;" ::: "memory");
    }

    const int lmm = tid >> 6;
    const int l64 = tid & 63;
    const __nv_bfloat16* lgb = (lmm == 0) ? kh : kl;
    const uint32_t lsm = (lmm == 0) ? 0u : (lmm == 1 ? (uint32_t)KMAT
                        : 2u * KMAT + (lmm == 3 ? 32u * KROWB : 0u));
    const int vrow0 = (lmm == 3) ? 32 : 0;

    #define ISSUE_KV(jt, buf) do {                                                  \
        uint32_t base_ = sb + (uint32_t)(buf) * KVSTAGE3 + lsm;                      \
        if (lmm < 2) {                                                               \
            const __nv_bfloat16* gp0_ = lgb + ((size_t)(b * Tt + (jt) * 64)) * Cc + h * Dd; \
            _Pragma("unroll")                                                        \
            for (int p_ = 0; p_ < 8; p_++) {                                         \
                int i_ = p_ * 64 + l64;                                              \
                int row_ = i_ >> 3, ch_ = i_ & 7;                                    \
                const void* gp_ = gp0_ + (size_t)row_ * Cc + ch_ * 8;                \
                uint32_t sp_ = base_ + (uint32_t)(row_ * KROWB + ch_ * 16);          \
                asm volatile("cp.async.cg.shared.global [%0], [%1], 16;"             \
                             :: "r"(sp_), "l"(gp_));                                 \
            }                                                                        \
        } else {                                                                     \
            const __half* gv0_ = v16 + ((size_t)(b * Tt + (jt) * 64 + vrow0)) * Cc + h * Dd; \
            _Pragma("unroll")                                                        \
            for (int p_ = 0; p_ < 4; p_++) {                                         \
                int i_ = p_ * 64 + l64;                                              \
                int row_ = i_ >> 3, ch_ = i_ & 7;                                    \
                const void* gp_ = gv0_ + (size_t)row_ * Cc + ch_ * 8;                \
                uint32_t sp_ = base_ + (uint32_t)(row_ * KROWB + ch_ * 16);          \
                asm volatile("cp.async.cg.shared.global [%0], [%1], 16;"             \
                             :: "r"(sp_), "l"(gp_));                                 \
            }                                                                        \
        }                                                                            \
        asm volatile("cp.async.commit_group;" ::: "memory");                         \
    } while (0)

    ISSUE_KV(0, 0);
    ISSUE_KV(1, 1);

    asm volatile("cp.async.wait_group 2;" ::: "memory");
    __syncthreads();

    uint32_t qhf[4][4], qlf[4][4];
    {
        const uint32_t qOff = sb + QOFF + (uint32_t)(wid * 16 + (lid & 15)) * KROWB
                              + (lid >> 4) * 16;
        #pragma unroll
        for (int kc = 0; kc < 4; kc++) {
            ldsm_x4(qhf[kc], qOff + kc * 32);
            ldsm_x4(qlf[kc], qOff + kc * 32 + QMAT);
        }
    }

    float o[8][4];
    #pragma unroll
    for (int nt = 0; nt < 8; nt++)
        #pragma unroll
        for (int c = 0; c < 4; c++) o[nt][c] = 0.f;
    float m0 = -1e30f, m1 = -1e30f, l0 = 0.f, l1 = 0.f;

    const uint32_t kOffL = (uint32_t)(((lid & 7) + ((lid >> 4) & 1) * 8)) * KROWB
                           + ((lid >> 3) & 1) * 16;
    const uint32_t vOffL = (uint32_t)(lid & 15) * KROWB + (lid >> 4) * 16;

    int buf = 0, nbuf = 2;
    for (int jt = 0; jt < NKV; jt++) {
        if (jt < NKV - 1) asm volatile("cp.async.wait_group 1;" ::: "memory");
        else              asm volatile("cp.async.wait_group 0;" ::: "memory");
        __syncthreads();
        if (jt + 2 < NKV) ISSUE_KV(jt + 2, nbuf);

        const uint32_t st = sb + (uint32_t)buf * KVSTAGE3;

        float s[8][4];
        #pragma unroll
        for (int nt = 0; nt < 8; nt++)
            #pragma unroll
            for (int c = 0; c < 4; c++) s[nt][c] = 0.f;

        #pragma unroll
        for (int kc = 0; kc < 4; kc++) {
            #pragma unroll
            for (int gp = 0; gp < 2; gp++) {
                uint32_t bh[2][4], bl[2][4];
                const uint32_t kb0 = st + kOffL + (uint32_t)(gp * 2) * 16 * KROWB + kc * 32;
                ldsm_x4(bh[0], kb0);
                ldsm_x4(bh[1], kb0 + 16 * KROWB);
                ldsm_x4(bl[0], kb0 + KMAT);
                ldsm_x4(bl[1], kb0 + KMAT + 16 * KROWB);
                #pragma unroll
                for (int j = 0; j < 2; j++)
                    #pragma unroll
                    for (int q = 0; q < 2; q++) {
                        mma16816(s[(gp * 2 + j) * 2 + q], qhf[kc], bh[j] + q * 2);
                        mma16816(s[(gp * 2 + j) * 2 + q], qhf[kc], bl[j] + q * 2);
                        mma16816(s[(gp * 2 + j) * 2 + q], qlf[kc], bh[j] + q * 2);
                    }
            }
        }

        float mt0 = -1e30f, mt1 = -1e30f;
        #pragma unroll
        for (int nt = 0; nt < 8; nt++) {
            mt0 = fmaxf(mt0, fmaxf(s[nt][0], s[nt][1]));
            mt1 = fmaxf(mt1, fmaxf(s[nt][2], s[nt][3]));
        }
        mt0 = fmaxf(mt0, __shfl_xor_sync(0xffffffffu, mt0, 1));
        mt0 = fmaxf(mt0, __shfl_xor_sync(0xffffffffu, mt0, 2));
        mt1 = fmaxf(mt1, __shfl_xor_sync(0xffffffffu, mt1, 1));
        mt1 = fmaxf(mt1, __shfl_xor_sync(0xffffffffu, mt1, 2));
        const float mn0 = fmaxf(m0, mt0), mn1 = fmaxf(m1, mt1);
        const float sc0 = __expf(m0 - mn0), sc1 = __expf(m1 - mn1);
        m0 = mn0; m1 = mn1;

        float ls0 = 0.f, ls1 = 0.f;
        #pragma unroll
        for (int nt = 0; nt < 8; nt++) {
            s[nt][0] = __expf(s[nt][0] - mn0);
            s[nt][1] = __expf(s[nt][1] - mn0);
            s[nt][2] = __expf(s[nt][2] - mn1);
            s[nt][3] = __expf(s[nt][3] - mn1);
            ls0 += s[nt][0] + s[nt][1];
            ls1 += s[nt][2] + s[nt][3];
        }
        ls0 += __shfl_xor_sync(0xffffffffu, ls0, 1);
        ls0 += __shfl_xor_sync(0xffffffffu, ls0, 2);
        ls1 += __shfl_xor_sync(0xffffffffu, ls1, 1);
        ls1 += __shfl_xor_sync(0xffffffffu, ls1, 2);
        l0 = l0 * sc0 + ls0;
        l1 = l1 * sc1 + ls1;

        #pragma unroll
        for (int nt = 0; nt < 8; nt++) {
            o[nt][0] *= sc0; o[nt][1] *= sc0;
            o[nt][2] *= sc1; o[nt][3] *= sc1;
        }

        uint32_t ph[4][4];
        #pragma unroll
        for (int kc = 0; kc < 4; kc++)
            #pragma unroll
            for (int half_ = 0; half_ < 2; half_++) {
                const int nt = kc * 2 + half_;
                ph[kc][half_ * 2 + 0] = h2_bits(__floats2half2_rn(s[nt][0], s[nt][1]));
                ph[kc][half_ * 2 + 1] = h2_bits(__floats2half2_rn(s[nt][2], s[nt][3]));
            }

        #pragma unroll
        for (int kc = 0; kc < 4; kc++) {
            #pragma unroll
            for (int gp = 0; gp < 2; gp++) {
                uint32_t bv[2][4];
                const uint32_t vb0 = st + 2u * KMAT + vOffL
                                     + (uint32_t)(kc * 16) * KROWB + (gp * 2) * 32;
                ldsm_x4_t(bv[0], vb0);
                ldsm_x4_t(bv[1], vb0 + 32);
                #pragma unroll
                for (int j = 0; j < 2; j++)
                    #pragma unroll
                    for (int q = 0; q < 2; q++)
                        mma16816h(o[(gp * 2 + j) * 2 + q], ph[kc], bv[j] + q * 2);
            }
        }

        buf = (buf == 2) ? 0 : buf + 1;
        nbuf = (nbuf == 2) ? 0 : nbuf + 1;
    }
    #undef ISSUE_KV

    const float inv0 = 1.0f / l0, inv1 = 1.0f / l1;
    const int r = lid >> 2;
    const int cq = (lid & 3) * 2;
    const size_t row0 = ((size_t)(b * STt + i0 + wid * 16 + r)) * Cc + h * Dd;
    const size_t row1 = row0 + 8 * Cc;
    #pragma unroll
    for (int nt = 0; nt < 8; nt++) {
        const int c = cq + nt * 8;
        *(__half2*)(y16 + row0 + c) = __floats2half2_rn(o[nt][0] * inv0, o[nt][1] * inv0);
        *(__half2*)(y16 + row1 + c) = __floats2half2_rn(o[nt][2] * inv1, o[nt][3] * inv1);
    }
}

// ---------------------------------------------------------------------------
extern "C" void kernel_launch(void* const* d_in, const int* in_sizes, int n_in,
                              void* d_out, int out_size)
{
    const float* x  = (const float*)d_in[0];
    const float* sx = (const float*)d_in[1];
    const float* Wq = (const float*)d_in[2];
    const float* Wk = (const float*)d_in[3];
    const float* Wv = (const float*)d_in[4];
    const float* Wc = (const float*)d_in[5];
    float* out = (float*)d_out;

    __nv_bfloat16 *xh, *xl, *sxh, *sxl, *qh, *ql, *kh, *kl;
    __nv_bfloat16 *wqh, *wql, *wkh, *wkl;
    __half *xh16, *xl16, *y16, *v16, *wv16, *wc16;
    cudaGetSymbolAddress((void**)&xh,  g_xh);  cudaGetSymbolAddress((void**)&xl,  g_xl);
    cudaGetSymbolAddress((void**)&sxh, g_sxh); cudaGetSymbolAddress((void**)&sxl, g_sxl);
    cudaGetSymbolAddress((void**)&qh,  g_qh);  cudaGetSymbolAddress((void**)&ql,  g_ql);
    cudaGetSymbolAddress((void**)&kh,  g_kh);  cudaGetSymbolAddress((void**)&kl,  g_kl);
    cudaGetSymbolAddress((void**)&wqh, g_wqh); cudaGetSymbolAddress((void**)&wql, g_wql);
    cudaGetSymbolAddress((void**)&wkh, g_wkh); cudaGetSymbolAddress((void**)&wkl, g_wkl);
    cudaGetSymbolAddress((void**)&xh16, g_xh16); cudaGetSymbolAddress((void**)&xl16, g_xl16);
    cudaGetSymbolAddress((void**)&y16, g_y16);
    cudaGetSymbolAddress((void**)&v16, g_v16);
    cudaGetSymbolAddress((void**)&wv16, g_wv16); cudaGetSymbolAddress((void**)&wc16, g_wc16);

    cudaFuncSetAttribute(proj_qkv, cudaFuncAttributeMaxDynamicSharedMemorySize, PROJ_SMEM);
    cudaFuncSetAttribute(gemm_mma_fp16x1, cudaFuncAttributeMaxDynamicSharedMemorySize, GEMM1_SMEM);
    cudaFuncSetAttribute(flash_mma, cudaFuncAttributeMaxDynamicSharedMemorySize, FLASH_SMEM);

    const int nbig = (MROWS * Cc) / 4;   // 2,097,152
    const int nwt  = (Cc * Cc) / 4;      // 262,144

    PJobs J;
    int off = 0;
    J.j[0] = { x,  (void*)xh,   (void*)xl, (void*)xh16, (void*)xl16, off, nbig, 3 }; off += nbig;
    J.j[1] = { sx, (void*)sxh,  (void*)sxl, nullptr, nullptr, off, nbig, 0 }; off += nbig;
    J.j[2] = { Wq, (void*)wqh,  (void*)wql, nullptr, nullptr, off, nwt,  0 }; off += nwt;
    J.j[3] = { Wk, (void*)wkh,  (void*)wkl, nullptr, nullptr, off, nwt,  0 }; off += nwt;
    J.j[4] = { Wv, (void*)wv16, nullptr, nullptr, nullptr, off, nwt,  2 }; off += nwt;
    J.j[5] = { Wc, (void*)wc16, nullptr, nullptr, nullptr, off, nwt,  2 }; off += nwt;
    prep_all<<<(off + 255) / 256, 256>>>(J);

    // interleaved 1D grid: 1536 CTAs, z = bid % 3 (q/k/v mixed per wave)
    proj_qkv<<<(Cc / BN) * (MROWS / BM) * 3, 256, PROJ_SMEM>>>(
        sxh, sxl, xh, xl, wqh, wql, wkh, wkl, xh16, xl16, wv16,
        qh, ql, kh, kl, v16);

    flash_mma<<<dim3(STt / 128, Hh, Bz), 256, FLASH_SMEM>>>(qh, ql, kh, kl, v16, y16);

    gemm_mma_fp16x1<<<dim3(Cc / BN, MROWS / BM), 256, GEMM1_SMEM>>>(y16, wc16, out);
}

// round 16
// speedup vs baseline: 1.5383x; 1.5383x over previous
#include <cuda_runtime.h>
#include <cuda_bf16.h>
#include <cuda_fp16.h>
#include <math.h>
#include <stdint.h>

#define Bz  4
#define Tt  2048
#define STt 2048
#define Cc  1024
#define Hh  16
#define Dd  64
#define MROWS (Bz * STt)   // 8192
#define GK 1024

// ---------------- scratch (static device arrays) ---------------------------
__device__ __nv_bfloat16 g_xh[(size_t)MROWS * Cc];
__device__ __nv_bfloat16 g_xl[(size_t)MROWS * Cc];
__device__ __nv_bfloat16 g_sxh[(size_t)MROWS * Cc];
__device__ __nv_bfloat16 g_sxl[(size_t)MROWS * Cc];
__device__ __nv_bfloat16 g_qh[(size_t)MROWS * Cc], g_ql[(size_t)MROWS * Cc];
__device__ __nv_bfloat16 g_kh[(size_t)MROWS * Cc], g_kl[(size_t)MROWS * Cc];
__device__ __nv_bfloat16 g_wqh[(size_t)Cc * Cc], g_wql[(size_t)Cc * Cc];
__device__ __nv_bfloat16 g_wkh[(size_t)Cc * Cc], g_wkl[(size_t)Cc * Cc];
// fp16 path
__device__ __half g_xh16[(size_t)MROWS * Cc], g_xl16[(size_t)MROWS * Cc];
__device__ __half g_y16[(size_t)MROWS * Cc];
__device__ __half g_v16[(size_t)MROWS * Cc];
__device__ __half g_wv16[(size_t)Cc * Cc], g_wc16[(size_t)Cc * Cc];

// ---------------- helpers ---------------------------------------------------
__device__ __forceinline__ uint32_t smem_u32(const void* p) {
    uint32_t a;
    asm("{ .reg .u64 t; cvta.to.shared.u64 t, %1; cvt.u32.u64 %0, t; }"
        : "=r"(a) : "l"(p));
    return a;
}
__device__ __forceinline__ void ldsm_x4(uint32_t* r, uint32_t addr) {
    asm volatile("ldmatrix.sync.aligned.m8n8.x4.shared.b16 {%0,%1,%2,%3}, [%4];"
                 : "=r"(r[0]), "=r"(r[1]), "=r"(r[2]), "=r"(r[3]) : "r"(addr));
}
__device__ __forceinline__ void ldsm_x4_t(uint32_t* r, uint32_t addr) {
    asm volatile("ldmatrix.sync.aligned.m8n8.x4.trans.shared.b16 {%0,%1,%2,%3}, [%4];"
                 : "=r"(r[0]), "=r"(r[1]), "=r"(r[2]), "=r"(r[3]) : "r"(addr));
}
__device__ __forceinline__ void mma16816(float* d, const uint32_t* a, const uint32_t* b) {
    asm volatile("mma.sync.aligned.m16n8k16.row.col.f32.bf16.bf16.f32 "
                 "{%0,%1,%2,%3}, {%4,%5,%6,%7}, {%8,%9}, {%0,%1,%2,%3};"
                 : "+f"(d[0]), "+f"(d[1]), "+f"(d[2]), "+f"(d[3])
                 : "r"(a[0]), "r"(a[1]), "r"(a[2]), "r"(a[3]), "r"(b[0]), "r"(b[1]));
}
__device__ __forceinline__ void mma16816h(float* d, const uint32_t* a, const uint32_t* b) {
    asm volatile("mma.sync.aligned.m16n8k16.row.col.f32.f16.f16.f32 "
                 "{%0,%1,%2,%3}, {%4,%5,%6,%7}, {%8,%9}, {%0,%1,%2,%3};"
                 : "+f"(d[0]), "+f"(d[1]), "+f"(d[2]), "+f"(d[3])
                 : "r"(a[0]), "r"(a[1]), "r"(a[2]), "r"(a[3]), "r"(b[0]), "r"(b[1]));
}
__device__ __forceinline__ uint32_t h2_bits(__half2 h) {
    union { __half2 h; uint32_t u; } cv; cv.h = h; return cv.u;
}

// ---------------------------------------------------------------------------
// One prep kernel. Modes: 0 bf16 hi/lo split, 2 fp16 round,
// 3 fused x: bf16 hi/lo + fp16 hi/lo from one read.
// ---------------------------------------------------------------------------
struct PJob { const float* s; void* h; void* l; void* h2; void* l2; int start; int n4; int mode; };
struct PJobs { PJob j[6]; };

__global__ void prep_all(PJobs J)
{
    int i = blockIdx.x * blockDim.x + threadIdx.x;
    #pragma unroll
    for (int w = 0; w < 6; w++) {
        const PJob jb = J.j[w];
        if (i >= jb.start && i < jb.start + jb.n4) {
            int k = i - jb.start;
            float4 v = ((const float4*)jb.s)[k];
            if (jb.mode == 0 || jb.mode == 3) {
                __nv_bfloat162* hp = (__nv_bfloat162*)jb.h;
                __nv_bfloat162* lp = (__nv_bfloat162*)jb.l;
                __nv_bfloat16 h0 = __float2bfloat16(v.x), h1 = __float2bfloat16(v.y);
                __nv_bfloat16 h2 = __float2bfloat16(v.z), h3 = __float2bfloat16(v.w);
                hp[2*k]   = __nv_bfloat162(h0, h1);
                hp[2*k+1] = __nv_bfloat162(h2, h3);
                lp[2*k]   = __nv_bfloat162(__float2bfloat16(v.x - __bfloat162float(h0)),
                                           __float2bfloat16(v.y - __bfloat162float(h1)));
                lp[2*k+1] = __nv_bfloat162(__float2bfloat16(v.z - __bfloat162float(h2)),
                                           __float2bfloat16(v.w - __bfloat162float(h3)));
            }
            if (jb.mode == 3) {
                __half2* hp = (__half2*)jb.h2;
                __half2* lp = (__half2*)jb.l2;
                __half2 H0 = __floats2half2_rn(v.x, v.y);
                __half2 H1 = __floats2half2_rn(v.z, v.w);
                hp[2*k] = H0; hp[2*k+1] = H1;
                lp[2*k] = __floats2half2_rn(v.x - __half2float(__low2half(H0)),
                                            v.y - __half2float(__high2half(H0)));
                lp[2*k+1] = __floats2half2_rn(v.z - __half2float(__low2half(H1)),
                                              v.w - __half2float(__high2half(H1)));
            }
            if (jb.mode == 2) {
                __half2* hp = (__half2*)jb.h;
                hp[2*k]   = __floats2half2_rn(v.x, v.y);
                hp[2*k+1] = __floats2half2_rn(v.z, v.w);
            }
            return;
        }
    }
}

// ---------------------------------------------------------------------------
// Tiling constants (BK=32, 80B rows)
// ---------------------------------------------------------------------------
#define BM 128
#define BN 128
#define BK 32
#define NST (GK / BK)                // 32
#define PADE 40
#define ROWB (PADE * 2)              // 80 B/row
#define MAT_BYTES (128 * ROWB)       // 10240
#define STAGE_BYTES (4 * MAT_BYTES)  // 40960 (bf16x3: Ah, Al, Wh, Wl)
#define STAGE3_BYTES (3 * MAT_BYTES) // 30720 (fp16x2: Ah, Al, W)
#define STAGE1_BYTES (2 * MAT_BYTES) // 20480 (fp16x1: A, W)
#define PROJ_SMEM (2 * STAGE_BYTES)  // 81920
#define GEMM1_SMEM (2 * STAGE1_BYTES) // 40960

// ---------------------------------------------------------------------------
// Merged q/k/v projections (R11/R12 grid: z slowest -> per-leg locality).
// z: 0=q, 1=k (bf16x3 ring-2), 2=v (fp16x2 ring-2)
// ---------------------------------------------------------------------------
__global__ __launch_bounds__(256, 2)
void proj_qkv(const __nv_bfloat16* __restrict__ sxh, const __nv_bfloat16* __restrict__ sxl,
              const __nv_bfloat16* __restrict__ xh,  const __nv_bfloat16* __restrict__ xl,
              const __nv_bfloat16* __restrict__ wqh, const __nv_bfloat16* __restrict__ wql,
              const __nv_bfloat16* __restrict__ wkh, const __nv_bfloat16* __restrict__ wkl,
              const __half* __restrict__ xh16, const __half* __restrict__ xl16,
              const __half* __restrict__ wv16,
              __nv_bfloat16* __restrict__ qhO, __nv_bfloat16* __restrict__ qlO,
              __nv_bfloat16* __restrict__ khO, __nv_bfloat16* __restrict__ klO,
              __half* __restrict__ v16O)
{
    extern __shared__ char dsm[];
    const uint32_t sb = smem_u32(dsm);

    const int tid = threadIdx.x;
    const int wid = tid >> 5, lid = tid & 31;
    const int wm = wid & 3, wn = wid >> 2;
    const int m0 = blockIdx.y * BM, n0 = blockIdx.x * BN;
    const int z  = blockIdx.z;

    const uint32_t aOff = (uint32_t)(wm * 32 + (lid & 15)) * ROWB + ((lid >> 4) * 8) * 2;
    const uint32_t bOff = 2u * MAT_BYTES
        + (uint32_t)(wn * 64 + ((lid >> 4) & 1) * 8 + (lid & 7)) * ROWB
        + (((lid >> 3) & 1) * 8) * 2;
    const int erow = m0 + wm * 32 + (lid >> 2);
    const int ecol = n0 + wn * 64 + (lid & 3) * 2;

    float acc[2][8][4];
    #pragma unroll
    for (int a = 0; a < 2; a++)
        #pragma unroll
        for (int b = 0; b < 8; b++)
            #pragma unroll
            for (int c = 0; c < 4; c++) acc[a][b][c] = 0.f;

    if (z < 2) {
        // ================= bf16x3 path (q or k), ring-2 =================
        const __nv_bfloat16* Ah = (z == 0) ? sxh : xh;
        const __nv_bfloat16* Al = (z == 0) ? sxl : xl;
        const __nv_bfloat16* Wh = (z == 0) ? wqh : wkh;
        const __nv_bfloat16* Wl = (z == 0) ? wql : wkl;
        __nv_bfloat16* OutH = (z == 0) ? qhO : khO;
        __nv_bfloat16* OutL = (z == 0) ? qlO : klO;

        const int lmm = tid >> 6;
        const int l64 = tid & 63;
        const __nv_bfloat16* lg = (lmm == 0) ? Ah : (lmm == 1) ? Al : (lmm == 2) ? Wh : Wl;
        const int lr0 = (lmm < 2) ? m0 : n0;
        const uint32_t lsm = (uint32_t)lmm * MAT_BYTES;

        #define ISSUE_STAGE(t, buf) do {                                              \
            uint32_t base_ = sb + (uint32_t)(buf) * STAGE_BYTES + lsm;                 \
            const __nv_bfloat16* gp0_ = lg + (size_t)lr0 * GK + (t) * BK;              \
            _Pragma("unroll")                                                          \
            for (int p_ = 0; p_ < 8; p_++) {                                           \
                int i_ = p_ * 64 + l64;                                                \
                int row_ = i_ >> 2, vec_ = i_ & 3;                                     \
                const void* gp_ = gp0_ + (size_t)row_ * GK + vec_ * 8;                 \
                uint32_t sp_ = base_ + (uint32_t)(row_ * ROWB + vec_ * 16);            \
                asm volatile("cp.async.cg.shared.global [%0], [%1], 16;"               \
                             :: "r"(sp_), "l"(gp_));                                   \
            }                                                                          \
            asm volatile("cp.async.commit_group;" ::: "memory");                       \
        } while (0)

        ISSUE_STAGE(0, 0);

        for (int t = 0; t < NST; t++) {
            asm volatile("cp.async.wait_group 0;" ::: "memory");
            __syncthreads();
            if (t + 1 < NST) ISSUE_STAGE(t + 1, (t + 1) & 1);

            const uint32_t st = sb + (uint32_t)(t & 1) * STAGE_BYTES;
            #pragma unroll
            for (int kk = 0; kk < 2; kk++) {
                const uint32_t ab = st + aOff + kk * 32;
                uint32_t ah0[4], ah1[4], al0[4], al1[4];
                ldsm_x4(ah0, ab);
                ldsm_x4(ah1, ab + 16 * ROWB);
                ldsm_x4(al0, ab + MAT_BYTES);
                ldsm_x4(al1, ab + MAT_BYTES + 16 * ROWB);

                const uint32_t bb = st + bOff + kk * 32;
                #pragma unroll
                for (int pp = 0; pp < 2; pp++) {
                    uint32_t bh[2][4], bl[2][4];
                    const uint32_t b0 = bb + (uint32_t)(pp * 2) * 16 * ROWB;
                    ldsm_x4(bh[0], b0);
                    ldsm_x4(bh[1], b0 + 16 * ROWB);
                    ldsm_x4(bl[0], b0 + MAT_BYTES);
                    ldsm_x4(bl[1], b0 + MAT_BYTES + 16 * ROWB);
                    #pragma unroll
                    for (int j = 0; j < 2; j++)
                        #pragma unroll
                        for (int q = 0; q < 2; q++) {
                            mma16816(acc[0][(pp * 2 + j) * 2 + q], ah0, bh[j] + q * 2);
                            mma16816(acc[1][(pp * 2 + j) * 2 + q], ah1, bh[j] + q * 2);
                            mma16816(acc[0][(pp * 2 + j) * 2 + q], ah0, bl[j] + q * 2);
                            mma16816(acc[1][(pp * 2 + j) * 2 + q], ah1, bl[j] + q * 2);
                            mma16816(acc[0][(pp * 2 + j) * 2 + q], al0, bh[j] + q * 2);
                            mma16816(acc[1][(pp * 2 + j) * 2 + q], al1, bh[j] + q * 2);
                        }
                }
            }
        }
        #undef ISSUE_STAGE

        #pragma unroll
        for (int mt = 0; mt < 2; mt++)
            #pragma unroll
            for (int nt = 0; nt < 8; nt++)
                #pragma unroll
                for (int rr = 0; rr < 2; rr++) {
                    float f0 = acc[mt][nt][rr * 2], f1 = acc[mt][nt][rr * 2 + 1];
                    __nv_bfloat16 h0 = __float2bfloat16(f0);
                    __nv_bfloat16 h1 = __float2bfloat16(f1);
                    size_t idx = (size_t)(erow + mt * 16 + rr * 8) * Cc + ecol + nt * 8;
                    *(__nv_bfloat162*)(OutH + idx) = __nv_bfloat162(h0, h1);
                    *(__nv_bfloat162*)(OutL + idx) =
                        __nv_bfloat162(__float2bfloat16(f0 - __bfloat162float(h0)),
                                       __float2bfloat16(f1 - __bfloat162float(h1)));
                }
    } else {
        // ================= fp16x2 path (v), ring-2 =================
        const int lmm = tid >> 6;
        const int l64 = tid & 63;
        const __half* lg = (lmm == 0) ? xh16 : (lmm == 1) ? xl16 : wv16;
        const int lr0 = (lmm < 2) ? m0 : (lmm == 2 ? n0 : n0 + 64);
        const uint32_t lsm = (lmm < 2) ? (uint32_t)lmm * MAT_BYTES
                                       : 2u * MAT_BYTES + (lmm == 3 ? 64u * ROWB : 0u);
        const int lit = (lmm < 2) ? 8 : 4;

        #define ISSUE_ST16(t, buf) do {                                               \
            uint32_t base_ = sb + (uint32_t)(buf) * STAGE3_BYTES + lsm;                \
            const __half* gp0_ = lg + (size_t)lr0 * GK + (t) * BK;                     \
            _Pragma("unroll")                                                          \
            for (int p_ = 0; p_ < 8; p_++) {                                           \
                if (p_ < lit) {                                                        \
                    int i_ = p_ * 64 + l64;                                            \
                    int row_ = i_ >> 2, vec_ = i_ & 3;                                 \
                    const void* gp_ = gp0_ + (size_t)row_ * GK + vec_ * 8;             \
                    uint32_t sp_ = base_ + (uint32_t)(row_ * ROWB + vec_ * 16);        \
                    asm volatile("cp.async.cg.shared.global [%0], [%1], 16;"           \
                                 :: "r"(sp_), "l"(gp_));                               \
                }                                                                      \
            }                                                                          \
            asm volatile("cp.async.commit_group;" ::: "memory");                       \
        } while (0)

        ISSUE_ST16(0, 0);

        for (int t = 0; t < NST; t++) {
            asm volatile("cp.async.wait_group 0;" ::: "memory");
            __syncthreads();
            if (t + 1 < NST) ISSUE_ST16(t + 1, (t + 1) & 1);

            const uint32_t st = sb + (uint32_t)(t & 1) * STAGE3_BYTES;
            #pragma unroll
            for (int kk = 0; kk < 2; kk++) {
                const uint32_t ab = st + aOff + kk * 32;
                uint32_t ah0[4], ah1[4], al0[4], al1[4];
                ldsm_x4(ah0, ab);
                ldsm_x4(ah1, ab + 16 * ROWB);
                ldsm_x4(al0, ab + MAT_BYTES);
                ldsm_x4(al1, ab + MAT_BYTES + 16 * ROWB);

                const uint32_t bb = st + bOff + kk * 32;
                #pragma unroll
                for (int pp = 0; pp < 2; pp++) {
                    uint32_t w[2][4];
                    const uint32_t b0 = bb + (uint32_t)(pp * 2) * 16 * ROWB;
                    ldsm_x4(w[0], b0);
                    ldsm_x4(w[1], b0 + 16 * ROWB);
                    #pragma unroll
                    for (int j = 0; j < 2; j++)
                        #pragma unroll
                        for (int q = 0; q < 2; q++) {
                            mma16816h(acc[0][(pp * 2 + j) * 2 + q], ah0, w[j] + q * 2);
                            mma16816h(acc[1][(pp * 2 + j) * 2 + q], ah1, w[j] + q * 2);
                            mma16816h(acc[0][(pp * 2 + j) * 2 + q], al0, w[j] + q * 2);
                            mma16816h(acc[1][(pp * 2 + j) * 2 + q], al1, w[j] + q * 2);
                        }
                }
            }
        }
        #undef ISSUE_ST16

        #pragma unroll
        for (int mt = 0; mt < 2; mt++)
            #pragma unroll
            for (int nt = 0; nt < 8; nt++) {
                *(__half2*)(v16O + (size_t)(erow + mt * 16) * Cc + ecol + nt * 8) =
                    __floats2half2_rn(acc[mt][nt][0], acc[mt][nt][1]);
                *(__half2*)(v16O + (size_t)(erow + mt * 16 + 8) * Cc + ecol + nt * 8) =
                    __floats2half2_rn(acc[mt][nt][2], acc[mt][nt][3]);
            }
    }
}

// ---------------------------------------------------------------------------
// fp16 1-term GEMM (out projection), BK=32, ring-2: Out = y16 @ Wc16^T.
// ---------------------------------------------------------------------------
__global__ __launch_bounds__(256, 2)
void gemm_mma_fp16x1(const __half* __restrict__ A,
                     const __half* __restrict__ W,
                     float* __restrict__ OutF)
{
    extern __shared__ char dsm[];
    const uint32_t sb = smem_u32(dsm);

    const int tid = threadIdx.x;
    const int wid = tid >> 5, lid = tid & 31;
    const int wm = wid & 3, wn = wid >> 2;
    const int m0 = blockIdx.y * BM, n0 = blockIdx.x * BN;

    const int lmm = tid >> 6;
    const int l64 = tid & 63;
    const __half* lg = (lmm < 2) ? A : W;
    const int lr0 = ((lmm == 0) ? m0 : (lmm == 1) ? m0 + 64 : (lmm == 2) ? n0 : n0 + 64);
    const uint32_t lsm = ((lmm & 1) ? 64u * ROWB : 0u) + ((lmm >= 2) ? (uint32_t)MAT_BYTES : 0u);

    float acc[2][8][4];
    #pragma unroll
    for (int a = 0; a < 2; a++)
        #pragma unroll
        for (int b = 0; b < 8; b++)
            #pragma unroll
            for (int c = 0; c < 4; c++) acc[a][b][c] = 0.f;

    const uint32_t aOff = (uint32_t)(wm * 32 + (lid & 15)) * ROWB + ((lid >> 4) * 8) * 2;
    const uint32_t bOff = 1u * MAT_BYTES
        + (uint32_t)(wn * 64 + ((lid >> 4) & 1) * 8 + (lid & 7)) * ROWB
        + (((lid >> 3) & 1) * 8) * 2;

    #define ISSUE_ST1(t, buf) do {                                                \
        uint32_t base_ = sb + (uint32_t)(buf) * STAGE1_BYTES + lsm;                \
        const __half* gp0_ = lg + (size_t)lr0 * GK + (t) * BK;                     \
        _Pragma("unroll")                                                          \
        for (int p_ = 0; p_ < 4; p_++) {                                           \
            int i_ = p_ * 64 + l64;                                                \
            int row_ = i_ >> 2, vec_ = i_ & 3;                                     \
            const void* gp_ = gp0_ + (size_t)row_ * GK + vec_ * 8;                 \
            uint32_t sp_ = base_ + (uint32_t)(row_ * ROWB + vec_ * 16);            \
            asm volatile("cp.async.cg.shared.global [%0], [%1], 16;"               \
                         :: "r"(sp_), "l"(gp_));                                   \
        }                                                                          \
        asm volatile("cp.async.commit_group;" ::: "memory");                       \
    } while (0)

    ISSUE_ST1(0, 0);

    for (int t = 0; t < NST; t++) {
        asm volatile("cp.async.wait_group 0;" ::: "memory");
        __syncthreads();
        if (t + 1 < NST) ISSUE_ST1(t + 1, (t + 1) & 1);

        const uint32_t st = sb + (uint32_t)(t & 1) * STAGE1_BYTES;
        #pragma unroll
        for (int kk = 0; kk < 2; kk++) {
            const uint32_t ab = st + aOff + kk * 32;
            uint32_t ah0[4], ah1[4];
            ldsm_x4(ah0, ab);
            ldsm_x4(ah1, ab + 16 * ROWB);

            const uint32_t bb = st + bOff + kk * 32;
            #pragma unroll
            for (int pp = 0; pp < 2; pp++) {
                uint32_t w[2][4];
                const uint32_t b0 = bb + (uint32_t)(pp * 2) * 16 * ROWB;
                ldsm_x4(w[0], b0);
                ldsm_x4(w[1], b0 + 16 * ROWB);
                #pragma unroll
                for (int j = 0; j < 2; j++)
                    #pragma unroll
                    for (int q = 0; q < 2; q++) {
                        mma16816h(acc[0][(pp * 2 + j) * 2 + q], ah0, w[j] + q * 2);
                        mma16816h(acc[1][(pp * 2 + j) * 2 + q], ah1, w[j] + q * 2);
                    }
            }
        }
    }
    #undef ISSUE_ST1

    const int erow = m0 + wm * 32 + (lid >> 2);
    const int ecol = n0 + wn * 64 + (lid & 3) * 2;
    #pragma unroll
    for (int mt = 0; mt < 2; mt++)
        #pragma unroll
        for (int nt = 0; nt < 8; nt++) {
            *(float2*)(OutF + (size_t)(erow + mt * 16) * Cc + ecol + nt * 8) =
                make_float2(acc[mt][nt][0], acc[mt][nt][1]);
            *(float2*)(OutF + (size_t)(erow + mt * 16 + 8) * Cc + ecol + nt * 8) =
                make_float2(acc[mt][nt][2], acc[mt][nt][3]);
        }
}

// ---------------------------------------------------------------------------
// Flash attention: QK^T bf16x3; PV single-fp16 P; single-fp16 y output.
// Ring-3 KV; Q region reused as KV buffer 2; 2 CTAs/SM.
// ---------------------------------------------------------------------------
#define KROWB 144
#define KMAT  (64 * KROWB)            // 9216
#define KVSTAGE3 (3 * KMAT)           // 27648
#define QMAT  (128 * KROWB)           // 18432
#define QOFF  (2 * KVSTAGE3)          // 55296 == start of KV buffer 2
#define FLASH_SMEM (QOFF + 2 * QMAT)  // 92160
#define NKV (Tt / 64)

__global__ __launch_bounds__(256, 2)
void flash_mma(const __nv_bfloat16* __restrict__ qh, const __nv_bfloat16* __restrict__ ql,
               const __nv_bfloat16* __restrict__ kh, const __nv_bfloat16* __restrict__ kl,
               const __half* __restrict__ v16,
               __half* __restrict__ y16)
{
    extern __shared__ char dsm[];
    const uint32_t sb = smem_u32(dsm);

    const int tid = threadIdx.x;
    const int wid = tid >> 5, lid = tid & 31;
    const int i0 = blockIdx.x * 128;
    const int h  = blockIdx.y;
    const int b  = blockIdx.z;

    {
        const int qm = tid >> 7;
        const int l128 = tid & 127;
        const __nv_bfloat16* qg = (qm == 0) ? qh : ql;
        const uint32_t qsm = sb + QOFF + (uint32_t)qm * QMAT;
        #pragma unroll
        for (int it = 0; it < 8; it++) {
            int idx = it * 128 + l128;
            int row = idx >> 3, ch = idx & 7;
            const void* gp = qg + ((size_t)(b * STt + i0 + row)) * Cc + h * Dd + ch * 8;
            uint32_t sp = qsm + (uint32_t)(row * KROWB + ch * 16);
            asm volatile("cp.async.cg.shared.global [%0], [%1], 16;" :: "r"(sp), "l"(gp));
        }
        asm volatile("cp.async.commit_group;" ::: "memory");
    }

    const int lmm = tid >> 6;
    const int l64 = tid & 63;
    const __nv_bfloat16* lgb = (lmm == 0) ? kh : kl;
    const uint32_t lsm = (lmm == 0) ? 0u : (lmm == 1 ? (uint32_t)KMAT
                        : 2u * KMAT + (lmm == 3 ? 32u * KROWB : 0u));
    const int vrow0 = (lmm == 3) ? 32 : 0;

    #define ISSUE_KV(jt, buf) do {                                                  \
        uint32_t base_ = sb + (uint32_t)(buf) * KVSTAGE3 + lsm;                      \
        if (lmm < 2) {                                                               \
            const __nv_bfloat16* gp0_ = lgb + ((size_t)(b * Tt + (jt) * 64)) * Cc + h * Dd; \
            _Pragma("unroll")                                                        \
            for (int p_ = 0; p_ < 8; p_++) {                                         \
                int i_ = p_ * 64 + l64;                                              \
                int row_ = i_ >> 3, ch_ = i_ & 7;                                    \
                const void* gp_ = gp0_ + (size_t)row_ * Cc + ch_ * 8;                \
                uint32_t sp_ = base_ + (uint32_t)(row_ * KROWB + ch_ * 16);          \
                asm volatile("cp.async.cg.shared.global [%0], [%1], 16;"             \
                             :: "r"(sp_), "l"(gp_));                                 \
            }                                                                        \
        } else {                                                                     \
            const __half* gv0_ = v16 + ((size_t)(b * Tt + (jt) * 64 + vrow0)) * Cc + h * Dd; \
            _Pragma("unroll")                                                        \
            for (int p_ = 0; p_ < 4; p_++) {                                         \
                int i_ = p_ * 64 + l64;                                              \
                int row_ = i_ >> 3, ch_ = i_ & 7;                                    \
                const void* gp_ = gv0_ + (size_t)row_ * Cc + ch_ * 8;                \
                uint32_t sp_ = base_ + (uint32_t)(row_ * KROWB + ch_ * 16);          \
                asm volatile("cp.async.cg.shared.global [%0], [%1], 16;"             \
                             :: "r"(sp_), "l"(gp_));                                 \
            }                                                                        \
        }                                                                            \
        asm volatile("cp.async.commit_group;" ::: "memory");                         \
    } while (0)

    ISSUE_KV(0, 0);
    ISSUE_KV(1, 1);

    asm volatile("cp.async.wait_group 2;" ::: "memory");
    __syncthreads();

    uint32_t qhf[4][4], qlf[4][4];
    {
        const uint32_t qOff = sb + QOFF + (uint32_t)(wid * 16 + (lid & 15)) * KROWB
                              + (lid >> 4) * 16;
        #pragma unroll
        for (int kc = 0; kc < 4; kc++) {
            ldsm_x4(qhf[kc], qOff + kc * 32);
            ldsm_x4(qlf[kc], qOff + kc * 32 + QMAT);
        }
    }

    float o[8][4];
    #pragma unroll
    for (int nt = 0; nt < 8; nt++)
        #pragma unroll
        for (int c = 0; c < 4; c++) o[nt][c] = 0.f;
    float m0 = -1e30f, m1 = -1e30f, l0 = 0.f, l1 = 0.f;

    const uint32_t kOffL = (uint32_t)(((lid & 7) + ((lid >> 4) & 1) * 8)) * KROWB
                           + ((lid >> 3) & 1) * 16;
    const uint32_t vOffL = (uint32_t)(lid & 15) * KROWB + (lid >> 4) * 16;

    int buf = 0, nbuf = 2;
    for (int jt = 0; jt < NKV; jt++) {
        if (jt < NKV - 1) asm volatile("cp.async.wait_group 1;" ::: "memory");
        else              asm volatile("cp.async.wait_group 0;" ::: "memory");
        __syncthreads();
        if (jt + 2 < NKV) ISSUE_KV(jt + 2, nbuf);

        const uint32_t st = sb + (uint32_t)buf * KVSTAGE3;

        float s[8][4];
        #pragma unroll
        for (int nt = 0; nt < 8; nt++)
            #pragma unroll
            for (int c = 0; c < 4; c++) s[nt][c] = 0.f;

        #pragma unroll
        for (int kc = 0; kc < 4; kc++) {
            #pragma unroll
            for (int gp = 0; gp < 2; gp++) {
                uint32_t bh[2][4], bl[2][4];
                const uint32_t kb0 = st + kOffL + (uint32_t)(gp * 2) * 16 * KROWB + kc * 32;
                ldsm_x4(bh[0], kb0);
                ldsm_x4(bh[1], kb0 + 16 * KROWB);
                ldsm_x4(bl[0], kb0 + KMAT);
                ldsm_x4(bl[1], kb0 + KMAT + 16 * KROWB);
                #pragma unroll
                for (int j = 0; j < 2; j++)
                    #pragma unroll
                    for (int q = 0; q < 2; q++) {
                        mma16816(s[(gp * 2 + j) * 2 + q], qhf[kc], bh[j] + q * 2);
                        mma16816(s[(gp * 2 + j) * 2 + q], qhf[kc], bl[j] + q * 2);
                        mma16816(s[(gp * 2 + j) * 2 + q], qlf[kc], bh[j] + q * 2);
                    }
            }
        }

        float mt0 = -1e30f, mt1 = -1e30f;
        #pragma unroll
        for (int nt = 0; nt < 8; nt++) {
            mt0 = fmaxf(mt0, fmaxf(s[nt][0], s[nt][1]));
            mt1 = fmaxf(mt1, fmaxf(s[nt][2], s[nt][3]));
        }
        mt0 = fmaxf(mt0, __shfl_xor_sync(0xffffffffu, mt0, 1));
        mt0 = fmaxf(mt0, __shfl_xor_sync(0xffffffffu, mt0, 2));
        mt1 = fmaxf(mt1, __shfl_xor_sync(0xffffffffu, mt1, 1));
        mt1 = fmaxf(mt1, __shfl_xor_sync(0xffffffffu, mt1, 2));
        const float mn0 = fmaxf(m0, mt0), mn1 = fmaxf(m1, mt1);
        const float sc0 = __expf(m0 - mn0), sc1 = __expf(m1 - mn1);
        m0 = mn0; m1 = mn1;

        float ls0 = 0.f, ls1 = 0.f;
        #pragma unroll
        for (int nt = 0; nt < 8; nt++) {
            s[nt][0] = __expf(s[nt][0] - mn0);
            s[nt][1] = __expf(s[nt][1] - mn0);
            s[nt][2] = __expf(s[nt][2] - mn1);
            s[nt][3] = __expf(s[nt][3] - mn1);
            ls0 += s[nt][0] + s[nt][1];
            ls1 += s[nt][2] + s[nt][3];
        }
        ls0 += __shfl_xor_sync(0xffffffffu, ls0, 1);
        ls0 += __shfl_xor_sync(0xffffffffu, ls0, 2);
        ls1 += __shfl_xor_sync(0xffffffffu, ls1, 1);
        ls1 += __shfl_xor_sync(0xffffffffu, ls1, 2);
        l0 = l0 * sc0 + ls0;
        l1 = l1 * sc1 + ls1;

        #pragma unroll
        for (int nt = 0; nt < 8; nt++) {
            o[nt][0] *= sc0; o[nt][1] *= sc0;
            o[nt][2] *= sc1; o[nt][3] *= sc1;
        }

        uint32_t ph[4][4];
        #pragma unroll
        for (int kc = 0; kc < 4; kc++)
            #pragma unroll
            for (int half_ = 0; half_ < 2; half_++) {
                const int nt = kc * 2 + half_;
                ph[kc][half_ * 2 + 0] = h2_bits(__floats2half2_rn(s[nt][0], s[nt][1]));
                ph[kc][half_ * 2 + 1] = h2_bits(__floats2half2_rn(s[nt][2], s[nt][3]));
            }

        #pragma unroll
        for (int kc = 0; kc < 4; kc++) {
            #pragma unroll
            for (int gp = 0; gp < 2; gp++) {
                uint32_t bv[2][4];
                const uint32_t vb0 = st + 2u * KMAT + vOffL
                                     + (uint32_t)(kc * 16) * KROWB + (gp * 2) * 32;
                ldsm_x4_t(bv[0], vb0);
                ldsm_x4_t(bv[1], vb0 + 32);
                #pragma unroll
                for (int j = 0; j < 2; j++)
                    #pragma unroll
                    for (int q = 0; q < 2; q++)
                        mma16816h(o[(gp * 2 + j) * 2 + q], ph[kc], bv[j] + q * 2);
            }
        }

        buf = (buf == 2) ? 0 : buf + 1;
        nbuf = (nbuf == 2) ? 0 : nbuf + 1;
    }
    #undef ISSUE_KV

    const float inv0 = 1.0f / l0, inv1 = 1.0f / l1;
    const int r = lid >> 2;
    const int cq = (lid & 3) * 2;
    const size_t row0 = ((size_t)(b * STt + i0 + wid * 16 + r)) * Cc + h * Dd;
    const size_t row1 = row0 + 8 * Cc;
    #pragma unroll
    for (int nt = 0; nt < 8; nt++) {
        const int c = cq + nt * 8;
        *(__half2*)(y16 + row0 + c) = __floats2half2_rn(o[nt][0] * inv0, o[nt][1] * inv0);
        *(__half2*)(y16 + row1 + c) = __floats2half2_rn(o[nt][2] * inv1, o[nt][3] * inv1);
    }
}

// ---------------------------------------------------------------------------
extern "C" void kernel_launch(void* const* d_in, const int* in_sizes, int n_in,
                              void* d_out, int out_size)
{
    const float* x  = (const float*)d_in[0];
    const float* sx = (const float*)d_in[1];
    const float* Wq = (const float*)d_in[2];
    const float* Wk = (const float*)d_in[3];
    const float* Wv = (const float*)d_in[4];
    const float* Wc = (const float*)d_in[5];
    float* out = (float*)d_out;

    __nv_bfloat16 *xh, *xl, *sxh, *sxl, *qh, *ql, *kh, *kl;
    __nv_bfloat16 *wqh, *wql, *wkh, *wkl;
    __half *xh16, *xl16, *y16, *v16, *wv16, *wc16;
    cudaGetSymbolAddress((void**)&xh,  g_xh);  cudaGetSymbolAddress((void**)&xl,  g_xl);
    cudaGetSymbolAddress((void**)&sxh, g_sxh); cudaGetSymbolAddress((void**)&sxl, g_sxl);
    cudaGetSymbolAddress((void**)&qh,  g_qh);  cudaGetSymbolAddress((void**)&ql,  g_ql);
    cudaGetSymbolAddress((void**)&kh,  g_kh);  cudaGetSymbolAddress((void**)&kl,  g_kl);
    cudaGetSymbolAddress((void**)&wqh, g_wqh); cudaGetSymbolAddress((void**)&wql, g_wql);
    cudaGetSymbolAddress((void**)&wkh, g_wkh); cudaGetSymbolAddress((void**)&wkl, g_wkl);
    cudaGetSymbolAddress((void**)&xh16, g_xh16); cudaGetSymbolAddress((void**)&xl16, g_xl16);
    cudaGetSymbolAddress((void**)&y16, g_y16);
    cudaGetSymbolAddress((void**)&v16, g_v16);
    cudaGetSymbolAddress((void**)&wv16, g_wv16); cudaGetSymbolAddress((void**)&wc16, g_wc16);

    cudaFuncSetAttribute(proj_qkv, cudaFuncAttributeMaxDynamicSharedMemorySize, PROJ_SMEM);
    cudaFuncSetAttribute(gemm_mma_fp16x1, cudaFuncAttributeMaxDynamicSharedMemorySize, GEMM1_SMEM);
    cudaFuncSetAttribute(flash_mma, cudaFuncAttributeMaxDynamicSharedMemorySize, FLASH_SMEM);

    const int nbig = (MROWS * Cc) / 4;   // 2,097,152
    const int nwt  = (Cc * Cc) / 4;      // 262,144

    PJobs J;
    int off = 0;
    J.j[0] = { x,  (void*)xh,   (void*)xl, (void*)xh16, (void*)xl16, off, nbig, 3 }; off += nbig;
    J.j[1] = { sx, (void*)sxh,  (void*)sxl, nullptr, nullptr, off, nbig, 0 }; off += nbig;
    J.j[2] = { Wq, (void*)wqh,  (void*)wql, nullptr, nullptr, off, nwt,  0 }; off += nwt;
    J.j[3] = { Wk, (void*)wkh,  (void*)wkl, nullptr, nullptr, off, nwt,  0 }; off += nwt;
    J.j[4] = { Wv, (void*)wv16, nullptr, nullptr, nullptr, off, nwt,  2 }; off += nwt;
    J.j[5] = { Wc, (void*)wc16, nullptr, nullptr, nullptr, off, nwt,  2 }; off += nwt;
    prep_all<<<(off + 255) / 256, 256>>>(J);

    proj_qkv<<<dim3(Cc / BN, MROWS / BM, 3), 256, PROJ_SMEM>>>(
        sxh, sxl, xh, xl, wqh, wql, wkh, wkl, xh16, xl16, wv16,
        qh, ql, kh, kl, v16);

    flash_mma<<<dim3(STt / 128, Hh, Bz), 256, FLASH_SMEM>>>(qh, ql, kh, kl, v16, y16);

    gemm_mma_fp16x1<<<dim3(Cc / BN, MROWS / BM), 256, GEMM1_SMEM>>>(y16, wc16, out);
}